// round 17
// baseline (speedup 1.0000x reference)
#include <cuda_runtime.h>
#include <cuda_fp16.h>
#include <cstdint>

#define NPTS 200000
#define DIM  128
#define KC   512
#define BN   128
#define CHN  128
#define NCH  (KC / CHN)

// ---------------- device scratch (allocation-free rule) ----------------
__device__ float g_sums[KC * DIM];
__device__ float g_counts[KC];
__device__ float g_c2[KC];
__device__ __half g_bh[KC * DIM];     // fp16 high part of centers
__device__ float g_cmmax2[64];        // per-prep-block max ||cm||^2
__device__ float g_chmax2[64];        // per-prep-block max ||ch||^2

// ---------------- SMEM layout (bytes) ----------------
#define RS     272                      // fp16 tile row stride (conflict-free ldmatrix)
#define FS     132                      // fp32 F tile row stride (floats)
#define OFF_ASSIGN 0                    // 128 int
#define OFF_LIST   512                  // 128 int (refine list)
#define OFF_CNT    1024                 // int
#define OFF_MX     1040                 // 2 floats: MAXCM, MAXCH
#define OFF_C2     2048                 // 512 floats
#define OFF_FN     4096                 // 128 floats ||f||
#define OFF_FMN    4608                 // 128 floats ||fm||
#define OFF_F32    5120                 // 128 x 132 floats = 67584
#define OFF_AH     72704                // 128 x RS = 34816
#define OFF_B      107520               // 2 bufs x 128 x RS = 69632
#define B_BUF      (CHN * RS)
#define SMEM_TOTAL 177152

__device__ __forceinline__ uint32_t smem_u32(const void* p) {
    uint32_t a;
    asm("{ .reg .u64 t; cvta.to.shared.u64 t, %1; cvt.u32.u64 %0, t; }" : "=r"(a) : "l"(p));
    return a;
}
__device__ __forceinline__ void ldsm4(uint32_t* r, uint32_t addr) {
    asm volatile("ldmatrix.sync.aligned.m8n8.x4.shared.b16 {%0,%1,%2,%3}, [%4];"
                 : "=r"(r[0]), "=r"(r[1]), "=r"(r[2]), "=r"(r[3]) : "r"(addr));
}
__device__ __forceinline__ void mma_f16(float* c, const uint32_t* a, uint32_t b0, uint32_t b1) {
    asm volatile(
        "mma.sync.aligned.m16n8k16.row.col.f32.f16.f16.f32 "
        "{%0,%1,%2,%3}, {%4,%5,%6,%7}, {%8,%9}, {%0,%1,%2,%3};"
        : "+f"(c[0]), "+f"(c[1]), "+f"(c[2]), "+f"(c[3])
        : "r"(a[0]), "r"(a[1]), "r"(a[2]), "r"(a[3]), "r"(b0), "r"(b1));
}
__device__ __forceinline__ void cp_async16(uint32_t dst, const void* src) {
    uint64_t g;
    asm("cvta.to.global.u64 %0, %1;" : "=l"(g) : "l"(src));
    asm volatile("cp.async.cg.shared.global [%0], [%1], 16;" :: "r"(dst), "l"(g) : "memory");
}
#define CP_COMMIT() asm volatile("cp.async.commit_group;" ::: "memory")
#define CP_WAIT1()  asm volatile("cp.async.wait_group 1;" ::: "memory")
#define CP_WAIT0()  asm volatile("cp.async.wait_group 0;" ::: "memory")

__device__ __forceinline__ uint32_t pack2h(__half a, __half b) {
    return (uint32_t)__half_as_ushort(a) | ((uint32_t)__half_as_ushort(b) << 16);
}

// ---------------- prep: zero scratch, c2, h split + residual norms ----------------
__global__ void prep_kernel(const float* __restrict__ centers) {
    __shared__ float s_cm[8], s_ch[8];
    const int tid = threadIdx.x;
    const int t = blockIdx.x * 256 + tid;
    *(float4*)(g_sums + t * 4) = make_float4(0.f, 0.f, 0.f, 0.f);
    if (t < KC) g_counts[t] = 0.0f;

    // warp per center: split to fp16, norms
    int c = blockIdx.x * 8 + (tid >> 5);
    int lane = tid & 31;
    float4 cv = ((const float4*)(centers + (size_t)c * DIM))[lane];
    float v[4] = {cv.x, cv.y, cv.z, cv.w};
    __half h[4];
    float c2 = 0.f, cm2 = 0.f, ch2 = 0.f;
    #pragma unroll
    for (int e = 0; e < 4; e++) {
        h[e] = __float2half_rn(v[e]);
        float hv = __half2float(h[e]);
        float r = v[e] - hv;
        c2  += v[e] * v[e];
        cm2 += r * r;
        ch2 += hv * hv;
    }
    ((uint2*)(g_bh + (size_t)c * DIM))[lane] =
        make_uint2(pack2h(h[0], h[1]), pack2h(h[2], h[3]));
    #pragma unroll
    for (int m = 16; m > 0; m >>= 1) {
        c2  += __shfl_xor_sync(0xffffffffu, c2, m);
        cm2 += __shfl_xor_sync(0xffffffffu, cm2, m);
        ch2 += __shfl_xor_sync(0xffffffffu, ch2, m);
    }
    if (lane == 0) {
        g_c2[c] = c2;
        s_cm[tid >> 5] = cm2;
        s_ch[tid >> 5] = ch2;
    }
    __syncthreads();
    if (tid == 0) {
        float mc = 0.f, mh = 0.f;
        #pragma unroll
        for (int i = 0; i < 8; i++) { mc = fmaxf(mc, s_cm[i]); mh = fmaxf(mh, s_ch[i]); }
        g_cmmax2[blockIdx.x] = mc;
        g_chmax2[blockIdx.x] = mh;
    }
}

// ---------------- B chunk loader: h split only, 128 rows via cp.async ----------------
__device__ __forceinline__ void load_chunk(uint32_t sb, int chunk, int buf, int tid) {
    #pragma unroll
    for (int i = 0; i < 8; i++) {
        int u = i * 256 + tid;            // 0..2047
        int r = u >> 4;                    // 0..127
        int q = u & 15;
        const __half* src = g_bh + ((size_t)(chunk * CHN + r)) * DIM + q * 8;
        uint32_t dst = sb + OFF_B + buf * B_BUF + r * RS + q * 16;
        cp_async16(dst, src);
    }
}

// ---------------- main fused kernel ----------------
__global__ __launch_bounds__(256, 1)
void assign_kernel(const float* __restrict__ F, const float* __restrict__ centers,
                   float* __restrict__ assign_out) {
    extern __shared__ char smem[];
    const uint32_t sb = smem_u32(smem);
    const int tid  = threadIdx.x;
    const int wid  = tid >> 5;
    const int lane = tid & 31;
    const long long gp0 = (long long)blockIdx.x * BN;

    if (tid == 0) *(int*)(smem + OFF_CNT) = 0;
    // c2 -> smem
    for (int i = tid; i < KC; i += 256) ((float*)(smem + OFF_C2))[i] = g_c2[i];
    // global residual maxima (warp 0)
    if (wid == 0) {
        float mc = fmaxf(g_cmmax2[lane], g_cmmax2[lane + 32]);
        float mh = fmaxf(g_chmax2[lane], g_chmax2[lane + 32]);
        #pragma unroll
        for (int m = 16; m > 0; m >>= 1) {
            mc = fmaxf(mc, __shfl_xor_sync(0xffffffffu, mc, m));
            mh = fmaxf(mh, __shfl_xor_sync(0xffffffffu, mh, m));
        }
        if (lane == 0) {
            ((float*)(smem + OFF_MX))[0] = sqrtf(mc);
            ((float*)(smem + OFF_MX))[1] = sqrtf(mh);
        }
    }

    // ---- Load + split A; keep fp32 copy; per-point norms ----
    {
        int row = tid >> 1, half = tid & 1;
        long long gp = gp0 + row;
        const float4* fr = (const float4*)(F + gp * DIM) + half * 16;
        float* f32row = (float*)(smem + OFF_F32) + row * FS + half * 64;
        float f2p = 0.f, fm2p = 0.f;
        #pragma unroll
        for (int g = 0; g < 8; g++) {
            float4 a = make_float4(0.f, 0.f, 0.f, 0.f), b = a;
            if (gp < NPTS) { a = fr[g * 2]; b = fr[g * 2 + 1]; }
            ((float4*)(f32row))[g * 2]     = a;
            ((float4*)(f32row))[g * 2 + 1] = b;
            float v[8] = {a.x, a.y, a.z, a.w, b.x, b.y, b.z, b.w};
            __half h[8];
            #pragma unroll
            for (int e = 0; e < 8; e++) {
                h[e] = __float2half_rn(v[e]);
                float r1 = v[e] - __half2float(h[e]);
                f2p  += v[e] * v[e];
                fm2p += r1 * r1;
            }
            uint32_t doff = OFF_AH + row * RS + (half * 64 + g * 8) * 2;
            *(uint4*)(smem + doff) = make_uint4(pack2h(h[0],h[1]), pack2h(h[2],h[3]),
                                                pack2h(h[4],h[5]), pack2h(h[6],h[7]));
        }
        float of2 = __shfl_xor_sync(0xffffffffu, f2p, 1);
        float ofm = __shfl_xor_sync(0xffffffffu, fm2p, 1);
        if (half == 0) {
            ((float*)(smem + OFF_FN))[row]  = sqrtf(f2p + of2);
            ((float*)(smem + OFF_FMN))[row] = sqrtf(fm2p + ofm);
        }
    }

    load_chunk(sb, 0, 0, tid);
    CP_COMMIT();

    // per-lane fragment offsets
    const int m0 = wid * 16;
    const int frow = (lane & 7) + ((lane >> 3) & 1) * 8;
    const int kblk = (lane >> 4) * 8;
    const uint32_t aoff = sb + OFF_AH + (uint32_t)((m0 + frow) * RS + kblk * 2);
    const uint32_t boff = sb + OFF_B + (uint32_t)(frow * RS + kblk * 2);

    float mv1[2] = {3.4e38f, 3.4e38f};   // best
    float mv2[2] = {3.4e38f, 3.4e38f};   // second-best (value only)
    int   mi1[2] = {0, 0};

    #pragma unroll 1
    for (int c = 0; c < NCH; c++) {
        const int buf = c & 1;
        if (c + 1 < NCH) { load_chunk(sb, c + 1, buf ^ 1, tid); CP_COMMIT(); CP_WAIT1(); }
        else             { CP_WAIT0(); }
        __syncthreads();

        float acc[16][4];
        #pragma unroll
        for (int nt = 0; nt < 16; nt++)
            #pragma unroll
            for (int r = 0; r < 4; r++) acc[nt][r] = 0.0f;

        const uint32_t bb = boff + buf * B_BUF;
        #pragma unroll
        for (int ks = 0; ks < 8; ks++) {
            uint32_t av[4];
            ldsm4(av, aoff + ks * 32);
            #pragma unroll
            for (int ntp = 0; ntp < 8; ntp++) {
                uint32_t bv[4];
                ldsm4(bv, bb + ntp * (16 * RS) + ks * 32);
                mma_f16(acc[2 * ntp],     av, bv[0], bv[2]);
                mma_f16(acc[2 * ntp + 1], av, bv[1], bv[3]);
            }
        }

        // score = c2 - 2*dot_hh; track (min1, idx1, min2)
        const float* c2s = (const float*)(smem + OFF_C2);
        #pragma unroll
        for (int nt = 0; nt < 16; nt++) {
            int n0 = c * CHN + nt * 8 + (lane & 3) * 2;
            float2 c2v = *(const float2*)(c2s + n0);
            float s0a = fmaf(-2.0f, acc[nt][0], c2v.x);
            float s1a = fmaf(-2.0f, acc[nt][1], c2v.y);
            float s0b = fmaf(-2.0f, acc[nt][2], c2v.x);
            float s1b = fmaf(-2.0f, acc[nt][3], c2v.y);
            if (s0a < mv1[0]) { mv2[0] = mv1[0]; mv1[0] = s0a; mi1[0] = n0; }
            else if (s0a < mv2[0]) mv2[0] = s0a;
            if (s1a < mv1[0]) { mv2[0] = mv1[0]; mv1[0] = s1a; mi1[0] = n0 + 1; }
            else if (s1a < mv2[0]) mv2[0] = s1a;
            if (s0b < mv1[1]) { mv2[1] = mv1[1]; mv1[1] = s0b; mi1[1] = n0; }
            else if (s0b < mv2[1]) mv2[1] = s0b;
            if (s1b < mv1[1]) { mv2[1] = mv1[1]; mv1[1] = s1b; mi1[1] = n0 + 1; }
            else if (s1b < mv2[1]) mv2[1] = s1b;
        }
        __syncthreads();   // all warps done with buf before overwrite
    }

    // ---- merge (min1, idx1, min2) across the 4 lanes of each row-quad ----
    #pragma unroll
    for (int m = 1; m <= 2; m <<= 1) {
        #pragma unroll
        for (int q = 0; q < 2; q++) {
            float o1 = __shfl_xor_sync(0xffffffffu, mv1[q], m);
            int   oi = __shfl_xor_sync(0xffffffffu, mi1[q], m);
            float o2 = __shfl_xor_sync(0xffffffffu, mv2[q], m);
            if (o1 < mv1[q] || (o1 == mv1[q] && oi < mi1[q])) {
                mv2[q] = fminf(o2, mv1[q]);
                mv1[q] = o1; mi1[q] = oi;
            } else {
                mv2[q] = fminf(mv2[q], o1);
            }
        }
    }

    // ---- flag or commit ----
    if ((lane & 3) == 0) {
        const float MAXCM = ((const float*)(smem + OFF_MX))[0];
        const float MAXCH = ((const float*)(smem + OFF_MX))[1];
        #pragma unroll
        for (int q = 0; q < 2; q++) {
            int pl = m0 + (lane >> 2) + q * 8;
            float fn  = ((const float*)(smem + OFF_FN))[pl];
            float fmn = ((const float*)(smem + OFF_FMN))[pl];
            // rigorous per-score bound (x2 for the pair comparison)
            float EP = 2.0f * (fn * MAXCM + fmn * (MAXCH + MAXCM)) + 2e-3f;
            if (mv2[q] - mv1[q] <= 2.0f * EP) {
                int slot = atomicAdd((int*)(smem + OFF_CNT), 1);
                ((int*)(smem + OFF_LIST))[slot] = pl;
            } else {
                ((int*)(smem + OFF_ASSIGN))[pl] = mi1[q];
                long long gp = gp0 + pl;
                if (assign_out != nullptr && gp < NPTS) assign_out[gp] = (float)mi1[q];
            }
        }
    }
    __syncthreads();

    // ---- exact fp32 refine for flagged points (one warp per point) ----
    {
        const int cnt = *(const int*)(smem + OFF_CNT);
        const float* c2s = (const float*)(smem + OFF_C2);
        for (int i = wid; i < cnt; i += 8) {
            int pt = ((const int*)(smem + OFF_LIST))[i];
            const float4* fp4 = (const float4*)((const float*)(smem + OFF_F32) + pt * FS);
            float best = 3.4e38f;
            int   bi = 0;
            #pragma unroll 1
            for (int j = 0; j < 16; j++) {
                int k = lane * 16 + j;
                const float4* cr = (const float4*)(centers + (size_t)k * DIM);
                float d0 = 0.f, d1 = 0.f;
                #pragma unroll
                for (int q = 0; q < 32; q += 2) {
                    float4 ca = cr[q],     fa = fp4[q];
                    float4 cb = cr[q + 1], fb = fp4[q + 1];
                    d0 = fmaf(ca.x, fa.x, d0); d0 = fmaf(ca.y, fa.y, d0);
                    d0 = fmaf(ca.z, fa.z, d0); d0 = fmaf(ca.w, fa.w, d0);
                    d1 = fmaf(cb.x, fb.x, d1); d1 = fmaf(cb.y, fb.y, d1);
                    d1 = fmaf(cb.z, fb.z, d1); d1 = fmaf(cb.w, fb.w, d1);
                }
                float s = fmaf(-2.0f, d0 + d1, c2s[k]);
                if (s < best) { best = s; bi = k; }
            }
            #pragma unroll
            for (int m = 16; m > 0; m >>= 1) {
                float ov = __shfl_xor_sync(0xffffffffu, best, m);
                int   oi = __shfl_xor_sync(0xffffffffu, bi, m);
                if (ov < best || (ov == best && oi < bi)) { best = ov; bi = oi; }
            }
            if (lane == 0) {
                ((int*)(smem + OFF_ASSIGN))[pt] = bi;
                long long gp = gp0 + pt;
                if (assign_out != nullptr && gp < NPTS) assign_out[gp] = (float)bi;
            }
        }
    }
    __syncthreads();

    // ---- segment sums from the fp32 smem tile ----
    {
        int pt = tid >> 1, half = tid & 1;
        long long gp = gp0 + pt;
        if (gp < NPTS) {
            int k = ((const int*)(smem + OFF_ASSIGN))[pt];
            float* dst = g_sums + (size_t)k * DIM;
            const float4* fr = (const float4*)((const float*)(smem + OFF_F32) + pt * FS + half * 64);
            #pragma unroll
            for (int i = 0; i < 16; i++) {
                float4 v = fr[i];
                asm volatile("red.global.add.v4.f32 [%0], {%1,%2,%3,%4};"
                             :: "l"(dst + half * 64 + i * 4),
                                "f"(v.x), "f"(v.y), "f"(v.z), "f"(v.w) : "memory");
            }
            if (half == 0)
                asm volatile("red.global.add.f32 [%0], %1;"
                             :: "l"(g_counts + k), "f"(1.0f) : "memory");
        }
    }
}

// new_centers = sums / max(counts, 1)
__global__ void finalize_kernel(float* __restrict__ out) {
    int i = blockIdx.x * blockDim.x + threadIdx.x;
    if (i < KC * DIM) {
        int k = i >> 7;
        out[i] = g_sums[i] / fmaxf(g_counts[k], 1.0f);
    }
}

extern "C" void kernel_launch(void* const* d_in, const int* in_sizes, int n_in,
                              void* d_out, int out_size) {
    const float* F       = (const float*)d_in[0];
    const float* centers = (const float*)d_in[1];
    float* out = (float*)d_out;
    float* assign_out = (out_size >= KC * DIM + NPTS) ? (out + KC * DIM) : nullptr;

    cudaFuncSetAttribute(assign_kernel, cudaFuncAttributeMaxDynamicSharedMemorySize,
                         SMEM_TOTAL);

    prep_kernel<<<64, 256>>>(centers);
    assign_kernel<<<(NPTS + BN - 1) / BN, 256, SMEM_TOTAL>>>(F, centers, assign_out);
    finalize_kernel<<<(KC * DIM + 255) / 256, 256>>>(out);
}